// round 9
// baseline (speedup 1.0000x reference)
#include <cuda_runtime.h>
#include <cuda_bf16.h>

// DimMasking R8: R3 structure + branchless predicated slow path.
//  - p <- p * (1-y)^{1/T}: degree-4 poly always; exact lg2/ex2 fix applied
//    via PREDICATED instructions (no BSSY/BSYNC branch regions at all)
//  - next-iteration sum fused into update loop (two accumulator trees)
//  - packed f32x2 (FFMA2) math, 1 row/warp, 8 rows/CTA, launch_bounds(256,5)

#define DD       640
#define HID      64
#define N_ITER   64
#define INV_T    (1.0f / 0.07f)
#define LOG2E    1.4426950408889634f
#define RPC      8
#define NP       10              // pairs per lane (640/32/2)
#define YT       0.02f

typedef unsigned long long u64;

__device__ __forceinline__ u64 fma2(u64 a, u64 b, u64 c) {
    u64 d; asm("fma.rn.f32x2 %0, %1, %2, %3;" : "=l"(d) : "l"(a), "l"(b), "l"(c)); return d;
}
__device__ __forceinline__ u64 mul2(u64 a, u64 b) {
    u64 d; asm("mul.rn.f32x2 %0, %1, %2;" : "=l"(d) : "l"(a), "l"(b)); return d;
}
__device__ __forceinline__ u64 add2(u64 a, u64 b) {
    u64 d; asm("add.rn.f32x2 %0, %1, %2;" : "=l"(d) : "l"(a), "l"(b)); return d;
}
__device__ __forceinline__ u64 pack2(float x, float y) {
    u64 r; asm("mov.b64 %0, {%1, %2};" : "=l"(r) : "f"(x), "f"(y)); return r;
}
__device__ __forceinline__ float2 unpack2(u64 v) {
    float2 f; asm("mov.b64 {%0, %1}, %2;" : "=f"(f.x), "=f"(f.y) : "l"(v)); return f;
}
__device__ __forceinline__ float ex2f(float x) {
    float r; asm("ex2.approx.ftz.f32 %0, %1;" : "=f"(r) : "f"(x)); return r;
}
__device__ __forceinline__ float rcpf(float x) {
    float r; asm("rcp.approx.ftz.f32 %0, %1;" : "=f"(r) : "f"(x)); return r;
}
__device__ __forceinline__ float warp_sum(float v) {
    #pragma unroll
    for (int o = 16; o > 0; o >>= 1)
        v += __shfl_xor_sync(0xffffffffu, v, o);
    return v;
}
__device__ __forceinline__ float warp_max(float v) {
    #pragma unroll
    for (int o = 16; o > 0; o >>= 1)
        v = fmaxf(v, __shfl_xor_sync(0xffffffffu, v, o));
    return v;
}

// If min(zx,zy) < -YT, overwrite both halves of f with the exact
// (1+z)^{1/T} = ex2(lg2(max(1+z,0)) * INV_T). Fully predicated: no branches.
__device__ __forceinline__ u64 slowfix(u64 z, u64 f) {
    float2 zf = unpack2(z);
    float2 ff = unpack2(f);
    asm volatile(
        "{\n\t"
        ".reg .pred p;\n\t"
        ".reg .f32 t, a;\n\t"
        "min.f32 t, %2, %3;\n\t"
        "setp.lt.f32 p, t, %4;\n\t"
        "@p add.f32 a, %2, 0f3F800000;\n\t"
        "@p max.f32 a, a, 0f00000000;\n\t"
        "@p lg2.approx.f32 a, a;\n\t"
        "@p mul.f32 a, a, %5;\n\t"
        "@p ex2.approx.f32 %0, a;\n\t"
        "@p add.f32 a, %3, 0f3F800000;\n\t"
        "@p max.f32 a, a, 0f00000000;\n\t"
        "@p lg2.approx.f32 a, a;\n\t"
        "@p mul.f32 a, a, %5;\n\t"
        "@p ex2.approx.f32 %1, a;\n\t"
        "}"
        : "+f"(ff.x), "+f"(ff.y)
        : "f"(zf.x), "f"(zf.y), "f"(-YT), "f"(INV_T));
    return pack2(ff.x, ff.y);
}

__global__ __launch_bounds__(RPC * 32, 5)
void dim_masking_kernel(const float* __restrict__ x,
                        const float* __restrict__ W1,
                        const float* __restrict__ b1,
                        const float* __restrict__ W2,
                        const float* __restrict__ b2,
                        float* __restrict__ out)
{
    __shared__ float2 xs2[RPC][DD / 2];
    __shared__ float2 hs2[RPC][HID / 2];

    const int w    = threadIdx.x >> 5;
    const int lane = threadIdx.x & 31;
    const int row  = blockIdx.x * RPC + w;

    const u64* xr = (const u64*)(x + (size_t)row * DD);

    // ---- stage x row into smem as pairs (coalesced) ----
    #pragma unroll
    for (int j = 0; j < NP; j++)
        *(u64*)&xs2[w][lane + 32 * j] = xr[lane + 32 * j];
    __syncwarp();

    const float* xsf = (const float*)xs2[w];

    // ---- GEMM1: hidden units (2*lane, 2*lane+1), packed FMA (R3 form) ----
    u64 acc1 = *(const u64*)&b1[2 * lane];
    #pragma unroll 8
    for (int d = 0; d < DD; d++) {
        float xd = xsf[d];
        acc1 = fma2(pack2(xd, xd), *(const u64*)&W1[d * HID + 2 * lane], acc1);
    }
    {
        float2 a = unpack2(acc1);
        hs2[w][lane] = make_float2(fmaxf(a.x, 0.0f), fmaxf(a.y, 0.0f));
    }
    __syncwarp();

    const float* hsf = (const float*)hs2[w];

    // ---- GEMM2: h pairs at dims 2*lane + 64*j (R3 form) ----
    u64 h2[NP];
    #pragma unroll
    for (int j = 0; j < NP; j++)
        h2[j] = *(const u64*)&b2[2 * lane + 64 * j];
    #pragma unroll 4
    for (int c = 0; c < HID; c++) {
        float hc = hsf[c];
        u64 hv = pack2(hc, hc);
        const float* w2r = &W2[c * DD + 2 * lane];
        #pragma unroll
        for (int j = 0; j < NP; j++)
            h2[j] = fma2(hv, *(const u64*)&w2r[64 * j], h2[j]);
    }

    // ---- init: p = exp2(l - max l); m = 1; running packed sum ----
    float lx[NP], ly[NP];
    float M0 = -3.402823e38f;
    #pragma unroll
    for (int j = 0; j < NP; j++) {
        float2 hf = unpack2(h2[j]);
        lx[j] = -hf.x * (INV_T * LOG2E);
        ly[j] = -hf.y * (INV_T * LOG2E);
        M0 = fmaxf(M0, fmaxf(lx[j], ly[j]));
    }
    M0 = warp_max(M0);

    u64 p[NP], m[NP];
    const u64 ONE2 = pack2(1.0f, 1.0f);
    u64 sacc = 0;
    #pragma unroll
    for (int j = 0; j < NP; j++) {
        p[j] = pack2(ex2f(lx[j] - M0), ex2f(ly[j] - M0));
        m[j] = ONE2;
        sacc = (j == 0) ? p[0] : add2(sacc, p[j]);
    }

    const u64 K1 = pack2(14.285714285714286f, 14.285714285714286f);
    const u64 K2 = pack2(94.89795918367347f,  94.89795918367347f);
    const u64 K3 = pack2(388.6297376093295f,  388.6297376093295f);
    const u64 K4 = pack2(1096.491194f,        1096.491194f);

    // ---- 64-iteration incremental recurrence (branchless body) ----
    #pragma unroll 1
    for (int it = 0; it < N_ITER; it++) {
        float2 sf = unpack2(sacc);
        float S = warp_sum(sf.x + sf.y);
        float nrS = -rcpf(S);
        u64 nrS2 = pack2(nrS, nrS);

        u64 sn0 = 0, sn1 = 0;
        #pragma unroll
        for (int j = 0; j < NP; j++) {
            u64 z = mul2(p[j], nrS2);            // z = -y, y = p/S
            u64 t = fma2(z, K4, K3);
            t = fma2(z, t, K2);
            t = fma2(z, t, K1);
            u64 f = fma2(z, t, ONE2);            // poly (1+z)^{1/T}, |z|<=0.02
            f = slowfix(z, f);                   // predicated exact overwrite
            p[j] = mul2(p[j], f);
            m[j] = fma2(z, m[j], m[j]);          // m *= (1 - y)
            if (j & 1) sn1 = (j == 1) ? p[1] : add2(sn1, p[j]);
            else       sn0 = (j == 0) ? p[0] : add2(sn0, p[j]);
        }
        sacc = add2(sn0, sn1);
    }

    // ---- out = m * x ----
    u64* orow = (u64*)(out + (size_t)row * DD);
    #pragma unroll
    for (int j = 0; j < NP; j++) {
        u64 xv = *(const u64*)&xs2[w][lane + 32 * j];
        orow[lane + 32 * j] = mul2(m[j], xv);
    }
}

extern "C" void kernel_launch(void* const* d_in, const int* in_sizes, int n_in,
                              void* d_out, int out_size)
{
    const float* x  = (const float*)d_in[0];   // (8192, 640)
    const float* W1 = (const float*)d_in[1];   // (640, 64)
    const float* b1 = (const float*)d_in[2];   // (64,)
    const float* W2 = (const float*)d_in[3];   // (64, 640)
    const float* b2 = (const float*)d_in[4];   // (640,)
    float* out = (float*)d_out;

    const int B = in_sizes[0] / DD;            // 8192
    dim_masking_kernel<<<B / RPC, RPC * 32>>>(x, W1, b1, W2, b2, out);
}

// round 10
// speedup vs baseline: 1.9458x; 1.9458x over previous
#include <cuda_runtime.h>
#include <cuda_bf16.h>

// DimMasking R9: 2 rows/warp (R7) + m-elimination.
//   m = (p/p0)^T exactly (same (1-y) factors, powers 1/T vs 1).
//   Track only q (rescaled p: q'=y*f, in [0,1]); L += lg2(S) per row;
//   lm = l - M0 cached in smem (reuses x staging); x reloaded at end;
//   m = ex2(T*(lg2(q*2^64) - 64 + L - lm)).
//   Branchy slow path (R8 predication was a 2.2x disaster). 128thr CTAs.

#define DD       640
#define HID      64
#define N_ITER   64
#define TEMP     0.07f
#define INV_T    (1.0f / 0.07f)
#define LOG2E    1.4426950408889634f
#define RPC      8               // rows per CTA (4 warps x 2)
#define NP       10              // pairs per lane per row
#define YT       0.02f

typedef unsigned long long u64;

__device__ __forceinline__ u64 fma2(u64 a, u64 b, u64 c) {
    u64 d; asm("fma.rn.f32x2 %0, %1, %2, %3;" : "=l"(d) : "l"(a), "l"(b), "l"(c)); return d;
}
__device__ __forceinline__ u64 mul2(u64 a, u64 b) {
    u64 d; asm("mul.rn.f32x2 %0, %1, %2;" : "=l"(d) : "l"(a), "l"(b)); return d;
}
__device__ __forceinline__ u64 add2(u64 a, u64 b) {
    u64 d; asm("add.rn.f32x2 %0, %1, %2;" : "=l"(d) : "l"(a), "l"(b)); return d;
}
__device__ __forceinline__ u64 pack2(float x, float y) {
    u64 r; asm("mov.b64 %0, {%1, %2};" : "=l"(r) : "f"(x), "f"(y)); return r;
}
__device__ __forceinline__ float2 unpack2(u64 v) {
    float2 f; asm("mov.b64 {%0, %1}, %2;" : "=f"(f.x), "=f"(f.y) : "l"(v)); return f;
}
__device__ __forceinline__ float ex2f(float x) {
    float r; asm("ex2.approx.ftz.f32 %0, %1;" : "=f"(r) : "f"(x)); return r;
}
__device__ __forceinline__ float lg2f(float x) {
    float r; asm("lg2.approx.ftz.f32 %0, %1;" : "=f"(r) : "f"(x)); return r;
}
__device__ __forceinline__ float rcpf(float x) {
    float r; asm("rcp.approx.ftz.f32 %0, %1;" : "=f"(r) : "f"(x)); return r;
}

__global__ __launch_bounds__(128, 5)
void dim_masking_kernel(const float* __restrict__ x,
                        const float* __restrict__ W1,
                        const float* __restrict__ b1,
                        const float* __restrict__ W2,
                        const float* __restrict__ b2,
                        float* __restrict__ out)
{
    // ls doubles as x staging (GEMM1) then holds lm = l - M0 for recovery.
    __shared__ __align__(16) float ls[RPC][DD];
    __shared__ __align__(16) float hs[RPC][HID];

    const int w    = threadIdx.x >> 5;     // 0..3
    const int lane = threadIdx.x & 31;
    const int ra   = 2 * w;
    const int rb   = 2 * w + 1;
    const int rowa = blockIdx.x * RPC + ra;

    const u64* xga = (const u64*)(x + (size_t)rowa * DD);
    const u64* xgb = (const u64*)(x + (size_t)(rowa + 1) * DD);

    // ---- stage both rows into smem ----
    #pragma unroll
    for (int j = 0; j < NP; j++) {
        *(u64*)&ls[ra][2 * (lane + 32 * j)] = xga[lane + 32 * j];
        *(u64*)&ls[rb][2 * (lane + 32 * j)] = xgb[lane + 32 * j];
    }
    __syncwarp();

    // ---- GEMM1: one W1 load feeds both rows ----
    const float4* xsa4 = (const float4*)ls[ra];
    const float4* xsb4 = (const float4*)ls[rb];
    u64 acca = *(const u64*)&b1[2 * lane];
    u64 accb = acca;
    #pragma unroll 2
    for (int d4 = 0; d4 < DD / 4; d4++) {
        float4 xa = xsa4[d4];
        float4 xb = xsb4[d4];
        const u64* w1r = (const u64*)&W1[(4 * d4) * HID + 2 * lane];
        u64 wv0 = w1r[0 * HID / 2];
        u64 wv1 = w1r[1 * HID / 2];
        u64 wv2 = w1r[2 * HID / 2];
        u64 wv3 = w1r[3 * HID / 2];
        acca = fma2(pack2(xa.x, xa.x), wv0, acca);
        accb = fma2(pack2(xb.x, xb.x), wv0, accb);
        acca = fma2(pack2(xa.y, xa.y), wv1, acca);
        accb = fma2(pack2(xb.y, xb.y), wv1, accb);
        acca = fma2(pack2(xa.z, xa.z), wv2, acca);
        accb = fma2(pack2(xb.z, xb.z), wv2, accb);
        acca = fma2(pack2(xa.w, xa.w), wv3, acca);
        accb = fma2(pack2(xb.w, xb.w), wv3, accb);
    }
    {
        float2 a = unpack2(acca);
        float2 b = unpack2(accb);
        hs[ra][2 * lane]     = fmaxf(a.x, 0.0f);
        hs[ra][2 * lane + 1] = fmaxf(a.y, 0.0f);
        hs[rb][2 * lane]     = fmaxf(b.x, 0.0f);
        hs[rb][2 * lane + 1] = fmaxf(b.y, 0.0f);
    }
    __syncwarp();

    // ---- GEMM2: one W2 load feeds both rows; accumulate into qa/qb ----
    u64 qa[NP], qb[NP];
    #pragma unroll
    for (int j = 0; j < NP; j++) {
        u64 bv = *(const u64*)&b2[2 * lane + 64 * j];
        qa[j] = bv;
        qb[j] = bv;
    }
    const float* hsa = hs[ra];
    const float* hsb = hs[rb];
    #pragma unroll 1
    for (int c = 0; c < HID; c++) {
        float hca = hsa[c];
        float hcb = hsb[c];
        u64 hva = pack2(hca, hca);
        u64 hvb = pack2(hcb, hcb);
        const float* w2r = &W2[c * DD + 2 * lane];
        #pragma unroll
        for (int j = 0; j < NP; j++) {
            u64 wv = *(const u64*)&w2r[64 * j];
            qa[j] = fma2(hva, wv, qa[j]);
            qb[j] = fma2(hvb, wv, qb[j]);
        }
    }

    // ---- logits l = -h*(1/T)*log2(e); row maxes ----
    const u64 NLT2 = pack2(-(INV_T * LOG2E), -(INV_T * LOG2E));
    float Ma = -3.402823e38f, Mb = Ma;
    #pragma unroll
    for (int j = 0; j < NP; j++) {
        qa[j] = mul2(qa[j], NLT2);
        qb[j] = mul2(qb[j], NLT2);
        float2 fa = unpack2(qa[j]);
        float2 fb = unpack2(qb[j]);
        Ma = fmaxf(Ma, fmaxf(fa.x, fa.y));
        Mb = fmaxf(Mb, fmaxf(fb.x, fb.y));
    }
    #pragma unroll
    for (int o = 16; o > 0; o >>= 1) {
        Ma = fmaxf(Ma, __shfl_xor_sync(0xffffffffu, Ma, o));
        Mb = fmaxf(Mb, __shfl_xor_sync(0xffffffffu, Mb, o));
    }

    // ---- lm = l - M -> smem (overwrites x staging); q = ex2(lm) ----
    u64 sacca = 0, saccb = 0;
    #pragma unroll
    for (int j = 0; j < NP; j++) {
        float2 fa = unpack2(qa[j]);
        float2 fb = unpack2(qb[j]);
        float lax = fa.x - Ma, lay = fa.y - Ma;
        float lbx = fb.x - Mb, lby = fb.y - Mb;
        *(u64*)&ls[ra][2 * (lane + 32 * j)] = pack2(lax, lay);
        *(u64*)&ls[rb][2 * (lane + 32 * j)] = pack2(lbx, lby);
        qa[j] = pack2(ex2f(lax), ex2f(lay));
        qb[j] = pack2(ex2f(lbx), ex2f(lby));
        sacca = (j == 0) ? qa[0] : add2(sacca, qa[j]);
        saccb = (j == 0) ? qb[0] : add2(saccb, qb[j]);
    }

    const u64 ONE2 = pack2(1.0f, 1.0f);
    const u64 K1 = pack2(14.285714285714286f, 14.285714285714286f);
    const u64 K2 = pack2(94.89795918367347f,  94.89795918367347f);
    const u64 K3 = pack2(388.6297376093295f,  388.6297376093295f);
    const u64 K4 = pack2(1096.491194f,        1096.491194f);

    float La = 0.0f, Lb = 0.0f;   // accumulated lg2 of rescale factors

    // ---- 64-iteration recurrence, two rows interleaved ----
    #pragma unroll 1
    for (int it = 0; it < N_ITER; it++) {
        float2 sfa = unpack2(sacca);
        float2 sfb = unpack2(saccb);
        float Sa = sfa.x + sfa.y;
        float Sb = sfb.x + sfb.y;
        #pragma unroll
        for (int o = 16; o > 0; o >>= 1) {
            Sa += __shfl_xor_sync(0xffffffffu, Sa, o);
            Sb += __shfl_xor_sync(0xffffffffu, Sb, o);
        }
        float rpa = rcpf(Sa);
        float rpb = rcpf(Sb);
        La += lg2f(Sa);
        Lb += lg2f(Sb);
        u64 nrA = pack2(-rpa, -rpa), prA = pack2(rpa, rpa);
        u64 nrB = pack2(-rpb, -rpb), prB = pack2(rpb, rpb);

        u64 snA = 0, snB = 0;
        #pragma unroll
        for (int j = 0; j < NP; j++) {
            u64 za = mul2(qa[j], nrA);           // z = -y
            u64 zb = mul2(qb[j], nrB);
            u64 ta = fma2(za, K4, K3);
            u64 tb = fma2(zb, K4, K3);
            ta = fma2(za, ta, K2);
            tb = fma2(zb, tb, K2);
            ta = fma2(za, ta, K1);
            tb = fma2(zb, tb, K1);
            u64 fa = fma2(za, ta, ONE2);         // poly (1+z)^{1/T}
            u64 fb = fma2(zb, tb, ONE2);
            float2 zaf = unpack2(za);
            float2 zbf = unpack2(zb);
            if (fminf(zaf.x, zaf.y) < -YT) {     // rare exact path (branchy)
                float2 ff = unpack2(fa);
                if (zaf.x < -YT) ff.x = ex2f(lg2f(fmaxf(1.0f + zaf.x, 0.0f)) * INV_T);
                if (zaf.y < -YT) ff.y = ex2f(lg2f(fmaxf(1.0f + zaf.y, 0.0f)) * INV_T);
                fa = pack2(ff.x, ff.y);
            }
            if (fminf(zbf.x, zbf.y) < -YT) {
                float2 ff = unpack2(fb);
                if (zbf.x < -YT) ff.x = ex2f(lg2f(fmaxf(1.0f + zbf.x, 0.0f)) * INV_T);
                if (zbf.y < -YT) ff.y = ex2f(lg2f(fmaxf(1.0f + zbf.y, 0.0f)) * INV_T);
                fb = pack2(ff.x, ff.y);
            }
            qa[j] = mul2(mul2(qa[j], fa), prA);  // q' = y*f  (rescaled)
            qb[j] = mul2(mul2(qb[j], fb), prB);
            snA = (j == 0) ? qa[0] : add2(snA, qa[j]);
            snB = (j == 0) ? qb[0] : add2(snB, qb[j]);
        }
        sacca = snA;
        saccb = snB;
    }

    // ---- recover m = ex2(T*(lg2(q*2^64) - 64 + L - lm)); out = m*x ----
    u64* ora = (u64*)(out + (size_t)rowa * DD);
    u64* orb = (u64*)(out + (size_t)(rowa + 1) * DD);
    const float SC = 18446744073709551616.0f;    // 2^64 (denormal rescue)
    const float CA = La - 64.0f;
    const float CB = Lb - 64.0f;
    #pragma unroll
    for (int j = 0; j < NP; j++) {
        float2 lma = unpack2(*(const u64*)&ls[ra][2 * (lane + 32 * j)]);
        float2 lmb = unpack2(*(const u64*)&ls[rb][2 * (lane + 32 * j)]);
        float2 qaf = unpack2(qa[j]);
        float2 qbf = unpack2(qb[j]);
        float max_ = ex2f((lg2f(qaf.x * SC) + CA - lma.x) * TEMP);
        float may_ = ex2f((lg2f(qaf.y * SC) + CA - lma.y) * TEMP);
        float mbx_ = ex2f((lg2f(qbf.x * SC) + CB - lmb.x) * TEMP);
        float mby_ = ex2f((lg2f(qbf.y * SC) + CB - lmb.y) * TEMP);
        u64 xa = xga[lane + 32 * j];             // x reload (L2-hot)
        u64 xb = xgb[lane + 32 * j];
        ora[lane + 32 * j] = mul2(pack2(max_, may_), xa);
        orb[lane + 32 * j] = mul2(pack2(mbx_, mby_), xb);
    }
}

extern "C" void kernel_launch(void* const* d_in, const int* in_sizes, int n_in,
                              void* d_out, int out_size)
{
    const float* x  = (const float*)d_in[0];   // (8192, 640)
    const float* W1 = (const float*)d_in[1];   // (640, 64)
    const float* b1 = (const float*)d_in[2];   // (64,)
    const float* W2 = (const float*)d_in[3];   // (64, 640)
    const float* b2 = (const float*)d_in[4];   // (640,)
    float* out = (float*)d_out;

    const int B = in_sizes[0] / DD;            // 8192
    dim_masking_kernel<<<B / RPC, 128>>>(x, W1, b1, W2, b2, out);
}

// round 12
// speedup vs baseline: 2.2629x; 1.1629x over previous
#include <cuda_runtime.h>
#include <cuda_bf16.h>

// DimMasking R10: R3 + big-block scan body.
//  - update loop split into 2 chunks of 5 pairs; straight-line z/poly/p/m
//    per chunk, ONE rare-branch guard per chunk (vs 10 per-pair branches)
//    -> ptxas can interleave 5 independent chains (ILP) instead of
//       serializing 10 tiny branch-fragmented blocks
//  - slow path reconstructs p from z (p_old = -z*S) then applies exact factor
//  - launch_bounds(256,3): ~84-reg budget so the interleave actually happens

#define DD       640
#define HID      64
#define N_ITER   64
#define INV_T    (1.0f / 0.07f)
#define LOG2E    1.4426950408889634f
#define RPC      8
#define NP       10              // pairs per lane (640/32/2)
#define CHUNK    5
#define YT       0.02f

typedef unsigned long long u64;

__device__ __forceinline__ u64 fma2(u64 a, u64 b, u64 c) {
    u64 d; asm("fma.rn.f32x2 %0, %1, %2, %3;" : "=l"(d) : "l"(a), "l"(b), "l"(c)); return d;
}
__device__ __forceinline__ u64 mul2(u64 a, u64 b) {
    u64 d; asm("mul.rn.f32x2 %0, %1, %2;" : "=l"(d) : "l"(a), "l"(b)); return d;
}
__device__ __forceinline__ u64 add2(u64 a, u64 b) {
    u64 d; asm("add.rn.f32x2 %0, %1, %2;" : "=l"(d) : "l"(a), "l"(b)); return d;
}
__device__ __forceinline__ u64 pack2(float x, float y) {
    u64 r; asm("mov.b64 %0, {%1, %2};" : "=l"(r) : "f"(x), "f"(y)); return r;
}
__device__ __forceinline__ float2 unpack2(u64 v) {
    float2 f; asm("mov.b64 {%0, %1}, %2;" : "=f"(f.x), "=f"(f.y) : "l"(v)); return f;
}
__device__ __forceinline__ float ex2f(float x) {
    float r; asm("ex2.approx.ftz.f32 %0, %1;" : "=f"(r) : "f"(x)); return r;
}
__device__ __forceinline__ float lg2f(float x) {
    float r; asm("lg2.approx.ftz.f32 %0, %1;" : "=f"(r) : "f"(x)); return r;
}
__device__ __forceinline__ float rcpf(float x) {
    float r; asm("rcp.approx.ftz.f32 %0, %1;" : "=f"(r) : "f"(x)); return r;
}
__device__ __forceinline__ float warp_sum(float v) {
    #pragma unroll
    for (int o = 16; o > 0; o >>= 1)
        v += __shfl_xor_sync(0xffffffffu, v, o);
    return v;
}
__device__ __forceinline__ float warp_max(float v) {
    #pragma unroll
    for (int o = 16; o > 0; o >>= 1)
        v = fmaxf(v, __shfl_xor_sync(0xffffffffu, v, o));
    return v;
}

__global__ __launch_bounds__(RPC * 32, 3)
void dim_masking_kernel(const float* __restrict__ x,
                        const float* __restrict__ W1,
                        const float* __restrict__ b1,
                        const float* __restrict__ W2,
                        const float* __restrict__ b2,
                        float* __restrict__ out)
{
    __shared__ float2 xs2[RPC][DD / 2];
    __shared__ float2 hs2[RPC][HID / 2];

    const int w    = threadIdx.x >> 5;
    const int lane = threadIdx.x & 31;
    const int row  = blockIdx.x * RPC + w;

    const u64* xr = (const u64*)(x + (size_t)row * DD);

    // ---- stage x row into smem as pairs (coalesced) ----
    #pragma unroll
    for (int j = 0; j < NP; j++)
        *(u64*)&xs2[w][lane + 32 * j] = xr[lane + 32 * j];
    __syncwarp();

    const float* xsf = (const float*)xs2[w];

    // ---- GEMM1: hidden units (2*lane, 2*lane+1), packed FMA (R3 form) ----
    u64 acc1 = *(const u64*)&b1[2 * lane];
    #pragma unroll 8
    for (int d = 0; d < DD; d++) {
        float xd = xsf[d];
        acc1 = fma2(pack2(xd, xd), *(const u64*)&W1[d * HID + 2 * lane], acc1);
    }
    {
        float2 a = unpack2(acc1);
        hs2[w][lane] = make_float2(fmaxf(a.x, 0.0f), fmaxf(a.y, 0.0f));
    }
    __syncwarp();

    const float* hsf = (const float*)hs2[w];

    // ---- GEMM2: h pairs at dims 2*lane + 64*j (R3 form) ----
    u64 h2[NP];
    #pragma unroll
    for (int j = 0; j < NP; j++)
        h2[j] = *(const u64*)&b2[2 * lane + 64 * j];
    #pragma unroll 4
    for (int c = 0; c < HID; c++) {
        float hc = hsf[c];
        u64 hv = pack2(hc, hc);
        const float* w2r = &W2[c * DD + 2 * lane];
        #pragma unroll
        for (int j = 0; j < NP; j++)
            h2[j] = fma2(hv, *(const u64*)&w2r[64 * j], h2[j]);
    }

    // ---- init: p = exp2(l - max l); m = 1; running packed sum ----
    float lx[NP], ly[NP];
    float M0 = -3.402823e38f;
    #pragma unroll
    for (int j = 0; j < NP; j++) {
        float2 hf = unpack2(h2[j]);
        lx[j] = -hf.x * (INV_T * LOG2E);
        ly[j] = -hf.y * (INV_T * LOG2E);
        M0 = fmaxf(M0, fmaxf(lx[j], ly[j]));
    }
    M0 = warp_max(M0);

    u64 p[NP], m[NP];
    const u64 ONE2 = pack2(1.0f, 1.0f);
    u64 sacc = 0;
    #pragma unroll
    for (int j = 0; j < NP; j++) {
        p[j] = pack2(ex2f(lx[j] - M0), ex2f(ly[j] - M0));
        m[j] = ONE2;
        sacc = (j == 0) ? p[0] : add2(sacc, p[j]);
    }

    const u64 K1 = pack2(14.285714285714286f, 14.285714285714286f);
    const u64 K2 = pack2(94.89795918367347f,  94.89795918367347f);
    const u64 K3 = pack2(388.6297376093295f,  388.6297376093295f);
    const u64 K4 = pack2(1096.491194f,        1096.491194f);

    // ---- 64-iteration incremental recurrence (2 branch regions/iter) ----
    #pragma unroll 1
    for (int it = 0; it < N_ITER; it++) {
        float2 sf = unpack2(sacc);
        float S = warp_sum(sf.x + sf.y);
        float nrS = -rcpf(S);
        u64 nrS2 = pack2(nrS, nrS);

        u64 sn0 = 0, sn1 = 0;
        #pragma unroll
        for (int c = 0; c < NP / CHUNK; c++) {
            u64 z[CHUNK];
            float zmx = 0.0f, zmy = 0.0f;       // z <= 0 always
            #pragma unroll
            for (int jj = 0; jj < CHUNK; jj++) {
                const int j = CHUNK * c + jj;
                z[jj] = mul2(p[j], nrS2);        // z = -y
                u64 t = fma2(z[jj], K4, K3);
                t = fma2(z[jj], t, K2);
                t = fma2(z[jj], t, K1);
                u64 f = fma2(z[jj], t, ONE2);    // poly (1+z)^{1/T}
                p[j] = mul2(p[j], f);            // tentative
                m[j] = fma2(z[jj], m[j], m[j]);  // m *= (1-y), exact
                float2 zf = unpack2(z[jj]);
                zmx = fminf(zmx, zf.x);
                zmy = fminf(zmy, zf.y);
            }
            if (fminf(zmx, zmy) < -YT) {         // rare: redo affected halves
                #pragma unroll
                for (int jj = 0; jj < CHUNK; jj++) {
                    const int j = CHUNK * c + jj;
                    float2 zf = unpack2(z[jj]);
                    float2 pf = unpack2(p[j]);
                    if (zf.x < -YT)
                        pf.x = (-zf.x) * S *
                               ex2f(lg2f(fmaxf(1.0f + zf.x, 0.0f)) * INV_T);
                    if (zf.y < -YT)
                        pf.y = (-zf.y) * S *
                               ex2f(lg2f(fmaxf(1.0f + zf.y, 0.0f)) * INV_T);
                    p[j] = pack2(pf.x, pf.y);
                }
            }
            #pragma unroll
            for (int jj = 0; jj < CHUNK; jj++) {
                const int j = CHUNK * c + jj;
                if (c == 0) sn0 = (jj == 0) ? p[j] : add2(sn0, p[j]);
                else        sn1 = (jj == 0) ? p[j] : add2(sn1, p[j]);
            }
        }
        sacc = add2(sn0, sn1);
    }

    // ---- out = m * x ----
    u64* orow = (u64*)(out + (size_t)row * DD);
    #pragma unroll
    for (int j = 0; j < NP; j++) {
        u64 xv = *(const u64*)&xs2[w][lane + 32 * j];
        orow[lane + 32 * j] = mul2(m[j], xv);
    }
}

extern "C" void kernel_launch(void* const* d_in, const int* in_sizes, int n_in,
                              void* d_out, int out_size)
{
    const float* x  = (const float*)d_in[0];   // (8192, 640)
    const float* W1 = (const float*)d_in[1];   // (640, 64)
    const float* b1 = (const float*)d_in[2];   // (64,)
    const float* W2 = (const float*)d_in[3];   // (64, 640)
    const float* b2 = (const float*)d_in[4];   // (640,)
    float* out = (float*)d_out;

    const int B = in_sizes[0] / DD;            // 8192
    dim_masking_kernel<<<B / RPC, RPC * 32>>>(x, W1, b1, W2, b2, out);
}